// round 5
// baseline (speedup 1.0000x reference)
#include <cuda_runtime.h>
#include <cuda_bf16.h>
#include <math.h>

// ------------------------- problem constants -------------------------
#define BB   512
#define NN   64
#define KK   16
#define ROWS (BB*NN)          // 32768
#define EPSV 1e-5f

// ------------------------- scratch (device globals) ------------------
__device__ float g_h0[ROWS*64];
__device__ float g_h1[ROWS*64];
__device__ float g_h2[ROWS*128];
__device__ float g_h3[ROWS*256];
__device__ float g_Abuf[ROWS*256];
__device__ float g_Bbuf[ROWS*256];
__device__ float g_Obuf[ROWS*256];
__device__ int   g_idxbuf[ROWS*KK];
__device__ float g_pool[BB*896];
__device__ float g_z1[BB*512];
__device__ float g_z2[BB*256];
__device__ float g_stats[4096];
__device__ float g_ss[4096];

// stage bases in g_stats/g_ss
#define ST0 0
#define ST1 128
#define ST2 256
#define ST3 384
#define ST4 640
#define ST5 896
#define ST6 1408
#define ST7 1920
#define ST8 2944

#define NEG_INF __int_as_float(0xff800000)

// ------------------------- f32x2 helpers ------------------------------
__device__ __forceinline__ unsigned long long lds_b64(unsigned addr) {
    unsigned long long v;
    asm volatile("ld.shared.b64 %0, [%1];" : "=l"(v) : "r"(addr));
    return v;
}
__device__ __forceinline__ unsigned long long packdup(float x) {
    unsigned long long v;
    asm("mov.b64 %0, {%1, %1};" : "=l"(v) : "f"(x));
    return v;
}
__device__ __forceinline__ unsigned long long fma2(unsigned long long a,
                                                   unsigned long long b,
                                                   unsigned long long c) {
    unsigned long long d;
    asm("fma.rn.f32x2 %0, %1, %2, %3;" : "=l"(d) : "l"(a), "l"(b), "l"(c));
    return d;
}
__device__ __forceinline__ void unpack2(unsigned long long v, float& lo, float& hi) {
    asm("mov.b64 {%0, %1}, %2;" : "=f"(lo), "=f"(hi) : "l"(v));
}
__device__ __forceinline__ unsigned smem_u32(const void* p) {
    return (unsigned)__cvta_generic_to_shared(p);
}

// ------------------------- kernels -----------------------------------

__global__ void k_zero_stats(float* stats) {
    for (int i = threadIdx.x; i < 4096; i += blockDim.x) stats[i] = 0.f;
}

// pre0 = x @ w_in  (32768x6 @ 6x64) + per-channel stats
__global__ void k_in_gemm(const float* __restrict__ x, const float* __restrict__ w,
                          float* __restrict__ pre, float* __restrict__ stats) {
    __shared__ float xs[128*6];
    __shared__ float wsm[6*64];
    __shared__ float red[4][64];
    int t = threadIdx.x;
    int r0 = blockIdx.x * 128;
    for (int e = t; e < 768; e += 256) xs[e] = x[r0*6 + e];
    for (int e = t; e < 384; e += 256) wsm[e] = w[e];
    __syncthreads();
    int m = t & 63, rg = t >> 6;
    float s = 0.f, s2 = 0.f;
    for (int r = rg; r < 128; r += 4) {
        float v = 0.f;
        #pragma unroll
        for (int k = 0; k < 6; k++) v += xs[r*6+k] * wsm[k*64+m];
        pre[(r0 + r)*64 + m] = v;
        s += v; s2 += v*v;
    }
    red[rg][m] = s; __syncthreads();
    if (rg == 0) atomicAdd(&stats[ST0 + m], red[0][m]+red[1][m]+red[2][m]+red[3][m]);
    __syncthreads();
    red[rg][m] = s2; __syncthreads();
    if (rg == 0) atomicAdd(&stats[ST0 + 64 + m], red[0][m]+red[1][m]+red[2][m]+red[3][m]);
}

__global__ void k_finalize(const float* __restrict__ stats, float* __restrict__ ss,
                           int base, int C, float invcnt,
                           const float* __restrict__ g, const float* __restrict__ b) {
    int c = blockIdx.x*blockDim.x + threadIdx.x;
    if (c >= C) return;
    float mean = stats[base + c] * invcnt;
    float var  = stats[base + C + c] * invcnt - mean*mean;
    float sc = g[c] * rsqrtf(var + EPSV);
    ss[base + c]     = sc;
    ss[base + C + c] = b[c] - mean*sc;
}

__global__ void k_apply(float* __restrict__ buf, const float* __restrict__ ss,
                        int base, int C, int total) {
    int i = blockIdx.x*blockDim.x + threadIdx.x;
    if (i >= total) return;
    int c = i & (C-1);
    float v = ss[base+c]*buf[i] + ss[base+C+c];
    buf[i] = v > 0.f ? v : 0.2f*v;
}

__global__ void k_apply_ec(const float* __restrict__ O, float* __restrict__ H,
                           const float* __restrict__ ss, int base, int C, int total) {
    int i = blockIdx.x*blockDim.x + threadIdx.x;
    if (i >= total) return;
    int c = i & (C-1);
    float v = O[i];
    float r;
    if (v == NEG_INF) r = 0.f;
    else { float z = ss[base+c]*v + ss[base+C+c]; r = z > 0.f ? z : 0.2f*z; }
    H[i] = r;
}

// ----- E1: per-batch KNN (double-precision distances) + A/B GEMMs + pre1 stats -----
template<int C_IN, int C_MID>
__global__ void k_e1(const float* __restrict__ X, const float* __restrict__ w_a,
                     float* __restrict__ gA, float* __restrict__ gB,
                     int* __restrict__ gidx, float* __restrict__ stats, int sbase)
{
    extern __shared__ float sm[];
    const int XST = C_IN + 1;
    float*  Xs    = sm;                          // 64*XST floats
    double* sqd   = (double*)(Xs + 64*XST);      // 64 doubles (offset mult of 8)
    int*    idx_s = (int*)(sqd + 64);            // 1024

    int b = blockIdx.x;
    int t = threadIdx.x;
    const float* Xb = X + (size_t)b*64*C_IN;

    for (int e = t; e < 64*C_IN; e += 256) {
        int i = e / C_IN, k = e % C_IN;
        Xs[i*XST + k] = Xb[e];
    }
    __syncthreads();
    if (t < 64) {
        double s = 0.0;
        for (int k = 0; k < C_IN; k++) { double v = Xs[t*XST+k]; s += v*v; }
        sqd[t] = s;
    }
    __syncthreads();

    // KNN: warp per row, iterative argmin, (d, index) tie-break, double accum
    {
        int w = t >> 5, l = t & 31;
        for (int i = w; i < 64; i += 8) {
            double d0 = 0.0, d1 = 0.0;
            for (int k = 0; k < C_IN; k++) {
                double xi = Xs[i*XST+k];
                d0 += xi * (double)Xs[l*XST+k];
                d1 += xi * (double)Xs[(l+32)*XST+k];
            }
            double my0 = sqd[i] + sqd[l]    - 2.0*d0;
            double my1 = sqd[i] + sqd[l+32] - 2.0*d1;
            for (int pick = 0; pick <= KK; pick++) {
                double dm; int jm;
                if (my0 <= my1) { dm = my0; jm = l; } else { dm = my1; jm = l+32; }
                #pragma unroll
                for (int off = 16; off; off >>= 1) {
                    double od = __shfl_xor_sync(0xffffffffu, dm, off);
                    int    oj = __shfl_xor_sync(0xffffffffu, jm, off);
                    if (od < dm || (od == dm && oj < jm)) { dm = od; jm = oj; }
                }
                if ((jm & 31) == l) { if (jm >= 32) my1 = 1e300; else my0 = 1e300; }
                if (pick > 0 && l == 0) {
                    idx_s[i*KK + pick - 1] = jm;
                    gidx[((size_t)b*64 + i)*KK + pick - 1] = jm;
                }
            }
        }
    }
    __syncthreads();

    // A = X@Wd, B = X@(Wn-Wd)  -> global
    {
        const int G = 256 / C_MID;
        const int IPG = 64 / G;
        int m = t % C_MID;
        int g = t / C_MID;
        for (int i0 = g*IPG; i0 < (g+1)*IPG; i0 += 8) {
            float aa[8], bb[8];
            #pragma unroll
            for (int ii = 0; ii < 8; ii++) { aa[ii]=0.f; bb[ii]=0.f; }
            for (int k = 0; k < C_IN; k++) {
                float wn  = w_a[k*C_MID + m];
                float wd  = w_a[(C_IN + k)*C_MID + m];
                float wnd = wn - wd;
                #pragma unroll
                for (int ii = 0; ii < 8; ii++) {
                    float xv = Xs[(i0+ii)*XST + k];
                    aa[ii] += xv * wd;
                    bb[ii] += xv * wnd;
                }
            }
            #pragma unroll
            for (int ii = 0; ii < 8; ii++) {
                gA[((size_t)b*64 + i0+ii)*C_MID + m] = aa[ii];
                gB[((size_t)b*64 + i0+ii)*C_MID + m] = bb[ii];
            }
        }
    }
    __syncthreads();

    // stats of pre1 = A[c] + B[idx[c,k]]
    {
        const float* Ab = gA + (size_t)b*64*C_MID;
        const float* Bb = gB + (size_t)b*64*C_MID;
        const int G = 256 / C_MID;
        int m = t % C_MID, rep = t / C_MID;
        float s = 0.f, s2 = 0.f;
        for (int r = rep; r < 64*KK; r += G) {
            int c = r >> 4;
            int nbr = idx_s[r];
            float v = Ab[c*C_MID + m] + Bb[nbr*C_MID + m];
            s += v; s2 += v*v;
        }
        atomicAdd(&stats[sbase + m], s);
        atomicAdd(&stats[sbase + C_MID + m], s2);
    }
}

// ----- E3: FFMA2 GEMM + inverse-list gather-max (no atomics), pre2 stats -----
template<int C_MID, int C_OUT>
__global__ void __launch_bounds__(256) k_e3(
                     const float* __restrict__ gA, const float* __restrict__ gB,
                     const int* __restrict__ gidx, const float* __restrict__ w_b,
                     const float* __restrict__ ss, int ssbase,
                     float* __restrict__ stats, int sbase,
                     float* __restrict__ O)
{
    extern __shared__ float sm[];
    const int RST = 68;
    float* Hs  = sm;                         // C_MID * 68  (transposed: Hs[m][r])
    float* Os  = Hs + C_MID*RST;             // 64 * 68 output tile
    float* scs = Os + 64*RST;                // C_MID
    float* shs = scs + C_MID;                // C_MID
    int* idx_s = (int*)(shs + C_MID);        // 1024
    int* offs  = idx_s + 1024;               // 1025
    int* fpos  = offs + 1025;                // 1024
    int* ent   = fpos + 1024;                // 1024

    int b  = blockIdx.x;
    int cb = blockIdx.y * 64;
    int t  = threadIdx.x;

    for (int e = t; e < 1024; e += 256) idx_s[e] = gidx[b*1024 + e];
    for (int e = t; e < C_MID; e += 256) {
        scs[e] = ss[ssbase + e];
        shs[e] = ss[ssbase + C_MID + e];
    }
    for (int e = t; e < 1024; e += 256) fpos[e] = 0;
    __syncthreads();
    // histogram rows by (tile, target point)
    for (int r = t; r < 1024; r += 256) atomicAdd(&fpos[(r>>6)*64 + idx_s[r]], 1);
    __syncthreads();
    if (t < 16) {
        int run = t*64;
        for (int n = 0; n < 64; n++) { int c = fpos[t*64+n]; offs[t*64+n] = run; run += c; }
    }
    if (t == 0) offs[1024] = 1024;
    __syncthreads();
    for (int e = t; e < 1024; e += 256) fpos[e] = offs[e];
    __syncthreads();
    for (int r = t; r < 1024; r += 256) {
        int p = atomicAdd(&fpos[(r>>6)*64 + idx_s[r]], 1);
        ent[p] = r & 63;
    }
    __syncthreads();

    const float4* Ab4 = (const float4*)(gA + (size_t)b*64*C_MID);
    const float4* Bb4 = (const float4*)(gB + (size_t)b*64*C_MID);
    const float4* Wg4 = (const float4*)(w_b + cb);
    const int WS4 = C_OUT >> 2;

    int cg = t & 15, rg = t >> 4, c0 = cg*4;   // GEMM role: rows rg*4..+3, channels c0..+3
    int gn = t & 63, gg = t >> 6;              // gather role: point gn, channels gg*16..+15
    float mx[16];
    #pragma unroll
    for (int j = 0; j < 16; j++) mx[j] = NEG_INF;
    float csum[4] = {0,0,0,0}, csq[4] = {0,0,0,0};

    unsigned hs_base = smem_u32(Hs) + rg*16;   // byte addr of Hs[0][rg*4]

    for (int tt = 0; tt < 16; tt++) {
        // ---- build H tile (transposed) ----
        {
            int r = t & 63, mg = t >> 6;
            int row = tt*64 + r;
            int cpt = row >> 4;
            int nbr = idx_s[row];
            const float4* Arow = Ab4 + cpt*(C_MID>>2);
            const float4* Brow = Bb4 + nbr*(C_MID>>2);
            #pragma unroll
            for (int m0 = 0; m0 < C_MID/16; m0++) {
                int m = m0*16 + mg*4;
                float4 a4 = Arow[m>>2];
                float4 b4 = Brow[m>>2];
                float v;
                v = scs[m+0]*(a4.x+b4.x)+shs[m+0]; Hs[(m+0)*RST + r] = v>0.f ? v : 0.2f*v;
                v = scs[m+1]*(a4.y+b4.y)+shs[m+1]; Hs[(m+1)*RST + r] = v>0.f ? v : 0.2f*v;
                v = scs[m+2]*(a4.z+b4.z)+shs[m+2]; Hs[(m+2)*RST + r] = v>0.f ? v : 0.2f*v;
                v = scs[m+3]*(a4.w+b4.w)+shs[m+3]; Hs[(m+3)*RST + r] = v>0.f ? v : 0.2f*v;
            }
        }
        __syncthreads();
        // ---- GEMM (FFMA2, 4 rows x 4 channels per thread) ----
        {
            unsigned long long acc[8];
            #pragma unroll
            for (int j = 0; j < 8; j++) acc[j] = 0ull;
            #pragma unroll 4
            for (int kk = 0; kk < C_MID; kk++) {
                unsigned addr = hs_base + kk*(RST*4);
                unsigned long long h01 = lds_b64(addr);
                unsigned long long h23 = lds_b64(addr + 8);
                float4 wv = __ldg(&Wg4[kk*WS4 + cg]);
                unsigned long long w0 = packdup(wv.x), w1 = packdup(wv.y);
                unsigned long long w2 = packdup(wv.z), w3 = packdup(wv.w);
                acc[0] = fma2(h01, w0, acc[0]);
                acc[1] = fma2(h01, w1, acc[1]);
                acc[2] = fma2(h01, w2, acc[2]);
                acc[3] = fma2(h01, w3, acc[3]);
                acc[4] = fma2(h23, w0, acc[4]);
                acc[5] = fma2(h23, w1, acc[5]);
                acc[6] = fma2(h23, w2, acc[6]);
                acc[7] = fma2(h23, w3, acc[7]);
            }
            float a[4][4];
            #pragma unroll
            for (int j = 0; j < 4; j++) {
                unpack2(acc[j],   a[0][j], a[1][j]);
                unpack2(acc[4+j], a[2][j], a[3][j]);
            }
            int rb = rg*4;
            #pragma unroll
            for (int i = 0; i < 4; i++) {
                #pragma unroll
                for (int j = 0; j < 4; j++) { float v = a[i][j]; csum[j] += v; csq[j] += v*v; }
                *(float4*)(Os + (rb+i)*RST + c0) = make_float4(a[i][0],a[i][1],a[i][2],a[i][3]);
            }
        }
        __syncthreads();
        // ---- gather-max over this tile's rows targeting point gn ----
        {
            int s0 = offs[tt*64 + gn];
            int s1 = offs[tt*64 + gn + 1];
            for (int p = s0; p < s1; p++) {
                int rr = ent[p];
                const float4* orow = (const float4*)(Os + rr*RST + gg*16);
                float4 v0 = orow[0], v1 = orow[1], v2 = orow[2], v3 = orow[3];
                mx[0] = fmaxf(mx[0], v0.x); mx[1] = fmaxf(mx[1], v0.y);
                mx[2] = fmaxf(mx[2], v0.z); mx[3] = fmaxf(mx[3], v0.w);
                mx[4] = fmaxf(mx[4], v1.x); mx[5] = fmaxf(mx[5], v1.y);
                mx[6] = fmaxf(mx[6], v1.z); mx[7] = fmaxf(mx[7], v1.w);
                mx[8] = fmaxf(mx[8], v2.x); mx[9] = fmaxf(mx[9], v2.y);
                mx[10]= fmaxf(mx[10],v2.z); mx[11]= fmaxf(mx[11],v2.w);
                mx[12]= fmaxf(mx[12],v3.x); mx[13]= fmaxf(mx[13],v3.y);
                mx[14]= fmaxf(mx[14],v3.z); mx[15]= fmaxf(mx[15],v3.w);
            }
        }
        __syncthreads();
    }
    #pragma unroll
    for (int j = 0; j < 4; j++) {
        atomicAdd(&stats[sbase + cb + c0 + j], csum[j]);
        atomicAdd(&stats[sbase + C_OUT + cb + c0 + j], csq[j]);
    }
    {
        float4* op = (float4*)(O + ((size_t)b*64 + gn)*C_OUT + cb + gg*16);
        op[0] = make_float4(mx[0], mx[1], mx[2], mx[3]);
        op[1] = make_float4(mx[4], mx[5], mx[6], mx[7]);
        op[2] = make_float4(mx[8], mx[9], mx[10],mx[11]);
        op[3] = make_float4(mx[12],mx[13],mx[14],mx[15]);
    }
}

// pooled = [mean_n h, max_n h]
__global__ void k_pool(const float* __restrict__ h1, const float* __restrict__ h2,
                       const float* __restrict__ h3, float* __restrict__ pool) {
    int b = blockIdx.x, t = threadIdx.x;
    for (int ch = t; ch < 448; ch += 256) {
        const float* src; int C, cc;
        if (ch < 64)       { src = h1; C = 64;  cc = ch; }
        else if (ch < 192) { src = h2; C = 128; cc = ch - 64; }
        else               { src = h3; C = 256; cc = ch - 192; }
        float s = 0.f, mxv = NEG_INF;
        for (int n = 0; n < 64; n++) {
            float v = src[((size_t)b*64 + n)*C + cc];
            s += v; mxv = fmaxf(mxv, v);
        }
        pool[b*896 + ch]       = s * (1.f/64.f);
        pool[b*896 + 448 + ch] = mxv;
    }
}

// classifier GEMM (tiled 16x16)
__global__ void k_gemm(const float* __restrict__ A, const float* __restrict__ W,
                       const float* __restrict__ bias, float* __restrict__ Cout,
                       int M, int Kd, int Nn, float* stats, int sbase) {
    __shared__ float as[16][17], ws[16][17];
    int tx = threadIdx.x, ty = threadIdx.y;
    int row = blockIdx.y*16 + ty;
    int col = blockIdx.x*16 + tx;
    float acc = 0.f;
    for (int k0 = 0; k0 < Kd; k0 += 16) {
        as[ty][tx] = (row < M && k0+tx < Kd) ? A[row*Kd + k0 + tx] : 0.f;
        ws[ty][tx] = (k0+ty < Kd && col < Nn) ? W[(k0+ty)*Nn + col] : 0.f;
        __syncthreads();
        #pragma unroll
        for (int kk = 0; kk < 16; kk++) acc += as[ty][kk]*ws[kk][tx];
        __syncthreads();
    }
    if (row < M && col < Nn) {
        if (bias) acc += bias[col];
        Cout[row*Nn + col] = acc;
        if (stats) {
            atomicAdd(&stats[sbase + col], acc);
            atomicAdd(&stats[sbase + Nn + col], acc*acc);
        }
    }
}

// ------------------------- host launcher -----------------------------
static inline size_t e1_smem(int cin) {
    return (size_t)(64*(cin+1))*4 + 64*8 + 1024*4;
}
static inline size_t e3_smem(int cmid) {
    return (size_t)(cmid*68 + 64*68 + 2*cmid)*4 + (size_t)(1024+1025+1024+1024)*4;
}

extern "C" void kernel_launch(void* const* d_in, const int* in_sizes, int n_in,
                              void* d_out, int out_size) {
    static const int ALPHA[31] = {30,7,26,17,6,20,11,0,21,12,1,22,13,2,23,14,3,
                                  24,15,4,25,16,5,27,18,8,28,19,9,29,10};
    const void* in[31];
    bool refOrder = (in_sizes[0] == ROWS*6);
    for (int i = 0; i < 31; i++) in[i] = refOrder ? d_in[i] : d_in[ALPHA[i]];

    const float* x    = (const float*)in[0];
    const float* w_in = (const float*)in[2];
    const float* g_in = (const float*)in[3];
    const float* b_in = (const float*)in[4];
    const float* w1a  = (const float*)in[5];
    const float* g1a  = (const float*)in[6];
    const float* b1a  = (const float*)in[7];
    const float* w1b  = (const float*)in[8];
    const float* g1b  = (const float*)in[9];
    const float* b1b  = (const float*)in[10];
    const float* w2a  = (const float*)in[11];
    const float* g2a  = (const float*)in[12];
    const float* b2a  = (const float*)in[13];
    const float* w2b  = (const float*)in[14];
    const float* g2b  = (const float*)in[15];
    const float* b2b  = (const float*)in[16];
    const float* w3a  = (const float*)in[17];
    const float* g3a  = (const float*)in[18];
    const float* b3a  = (const float*)in[19];
    const float* w3b  = (const float*)in[20];
    const float* g3b  = (const float*)in[21];
    const float* b3b  = (const float*)in[22];
    const float* wc1  = (const float*)in[23];
    const float* gc1  = (const float*)in[24];
    const float* bc1  = (const float*)in[25];
    const float* wc2  = (const float*)in[26];
    const float* gc2  = (const float*)in[27];
    const float* bc2  = (const float*)in[28];
    const float* wc3  = (const float*)in[29];
    const float* bc3  = (const float*)in[30];
    float* out = (float*)d_out;

    float *h0, *h1, *h2, *h3, *Abuf, *Bbuf, *Obuf, *pool, *z1, *z2, *stats, *ss;
    int* idxp;
    cudaGetSymbolAddress((void**)&h0, g_h0);
    cudaGetSymbolAddress((void**)&h1, g_h1);
    cudaGetSymbolAddress((void**)&h2, g_h2);
    cudaGetSymbolAddress((void**)&h3, g_h3);
    cudaGetSymbolAddress((void**)&Abuf, g_Abuf);
    cudaGetSymbolAddress((void**)&Bbuf, g_Bbuf);
    cudaGetSymbolAddress((void**)&Obuf, g_Obuf);
    cudaGetSymbolAddress((void**)&idxp, g_idxbuf);
    cudaGetSymbolAddress((void**)&pool, g_pool);
    cudaGetSymbolAddress((void**)&z1, g_z1);
    cudaGetSymbolAddress((void**)&z2, g_z2);
    cudaGetSymbolAddress((void**)&stats, g_stats);
    cudaGetSymbolAddress((void**)&ss, g_ss);

    cudaFuncSetAttribute(k_e1<64,64>,   cudaFuncAttributeMaxDynamicSharedMemorySize, (int)e1_smem(64));
    cudaFuncSetAttribute(k_e1<64,128>,  cudaFuncAttributeMaxDynamicSharedMemorySize, (int)e1_smem(64));
    cudaFuncSetAttribute(k_e1<128,256>, cudaFuncAttributeMaxDynamicSharedMemorySize, (int)e1_smem(128));
    cudaFuncSetAttribute(k_e3<64,64>,   cudaFuncAttributeMaxDynamicSharedMemorySize, (int)e3_smem(64));
    cudaFuncSetAttribute(k_e3<128,128>, cudaFuncAttributeMaxDynamicSharedMemorySize, (int)e3_smem(128));
    cudaFuncSetAttribute(k_e3<256,256>, cudaFuncAttributeMaxDynamicSharedMemorySize, (int)e3_smem(256));

    k_zero_stats<<<1, 256>>>(stats);

    // stage 0: input MLP
    k_in_gemm<<<256, 256>>>(x, w_in, h0, stats);
    k_finalize<<<1, 512>>>(stats, ss, ST0, 64, 1.f/ROWS, g_in, b_in);
    k_apply<<<ROWS*64/256, 256>>>(h0, ss, ST0, 64, ROWS*64);

    // conv1
    k_e1<64,64><<<BB, 256, e1_smem(64)>>>(h0, w1a, Abuf, Bbuf, idxp, stats, ST1);
    k_finalize<<<1, 512>>>(stats, ss, ST1, 64, 1.f/(ROWS*KK), g1a, b1a);
    k_e3<64,64><<<dim3(BB,1), 256, e3_smem(64)>>>(Abuf, Bbuf, idxp, w1b, ss, ST1, stats, ST2, Obuf);
    k_finalize<<<1, 512>>>(stats, ss, ST2, 64, 1.f/(ROWS*KK), g1b, b1b);
    k_apply_ec<<<ROWS*64/256, 256>>>(Obuf, h1, ss, ST2, 64, ROWS*64);

    // conv2
    k_e1<64,128><<<BB, 256, e1_smem(64)>>>(h1, w2a, Abuf, Bbuf, idxp, stats, ST3);
    k_finalize<<<1, 512>>>(stats, ss, ST3, 128, 1.f/(ROWS*KK), g2a, b2a);
    k_e3<128,128><<<dim3(BB,2), 256, e3_smem(128)>>>(Abuf, Bbuf, idxp, w2b, ss, ST3, stats, ST4, Obuf);
    k_finalize<<<1, 512>>>(stats, ss, ST4, 128, 1.f/(ROWS*KK), g2b, b2b);
    k_apply_ec<<<ROWS*128/256, 256>>>(Obuf, h2, ss, ST4, 128, ROWS*128);

    // conv3
    k_e1<128,256><<<BB, 256, e1_smem(128)>>>(h2, w3a, Abuf, Bbuf, idxp, stats, ST5);
    k_finalize<<<1, 512>>>(stats, ss, ST5, 256, 1.f/(ROWS*KK), g3a, b3a);
    k_e3<256,256><<<dim3(BB,4), 256, e3_smem(256)>>>(Abuf, Bbuf, idxp, w3b, ss, ST5, stats, ST6, Obuf);
    k_finalize<<<1, 512>>>(stats, ss, ST6, 256, 1.f/(ROWS*KK), g3b, b3b);
    k_apply_ec<<<ROWS*256/256, 256>>>(Obuf, h3, ss, ST6, 256, ROWS*256);

    // pooling + classifier
    k_pool<<<BB, 256>>>(h1, h2, h3, pool);

    k_gemm<<<dim3(512/16, BB/16), dim3(16,16)>>>(pool, wc1, nullptr, z1, BB, 896, 512, stats, ST7);
    k_finalize<<<1, 512>>>(stats, ss, ST7, 512, 1.f/BB, gc1, bc1);
    k_apply<<<BB*512/256, 256>>>(z1, ss, ST7, 512, BB*512);

    k_gemm<<<dim3(256/16, BB/16), dim3(16,16)>>>(z1, wc2, nullptr, z2, BB, 512, 256, stats, ST8);
    k_finalize<<<1, 512>>>(stats, ss, ST8, 256, 1.f/BB, gc2, bc2);
    k_apply<<<BB*256/256, 256>>>(z2, ss, ST8, 256, BB*256);

    k_gemm<<<dim3(1, BB/16), dim3(16,16)>>>(z2, wc3, bc3, out, BB, 256, 2, nullptr, 0);
}

// round 7
// speedup vs baseline: 1.3857x; 1.3857x over previous
#include <cuda_runtime.h>
#include <cuda_bf16.h>
#include <math.h>

// ------------------------- problem constants -------------------------
#define BB   512
#define NN   64
#define KK   16
#define ROWS (BB*NN)          // 32768
#define EPSV 1e-5f

// ------------------------- scratch (device globals) ------------------
__device__ float g_h0[ROWS*64];
__device__ float g_h1[ROWS*64];
__device__ float g_h2[ROWS*128];
__device__ float g_h3[ROWS*256];
__device__ float g_Abuf[ROWS*256];
__device__ float g_Bbuf[ROWS*256];
__device__ float g_Obuf[ROWS*256];
__device__ int   g_idxbuf[ROWS*KK];
__device__ float g_pool[BB*896];
__device__ float g_z1[BB*512];
__device__ float g_z2[BB*256];
__device__ float g_stats[4096];
__device__ float g_ss[4096];

// stage bases in g_stats/g_ss
#define ST0 0
#define ST1 128
#define ST2 256
#define ST3 384
#define ST4 640
#define ST5 896
#define ST6 1408
#define ST7 1920
#define ST8 2944

__device__ __forceinline__ unsigned enc_f(float f) {
    unsigned u = __float_as_uint(f);
    return (u & 0x80000000u) ? ~u : (u | 0x80000000u);
}
__device__ __forceinline__ float dec_f(unsigned u) {
    return (u & 0x80000000u) ? __uint_as_float(u ^ 0x80000000u) : __uint_as_float(~u);
}
#define NEG_INF __int_as_float(0xff800000)

// Kahan step with exact-product correction: (s,c) += a*b
__device__ __forceinline__ void kahan_fma(float a, float b, float& s, float& c) {
    float p  = __fmul_rn(a, b);
    float pe = __fmaf_rn(a, b, -p);          // exact low part of a*b
    c = __fsub_rn(c, pe);
    float y  = __fsub_rn(p, c);
    float tn = __fadd_rn(s, y);
    c = __fsub_rn(__fsub_rn(tn, s), y);
    s = tn;
}

// ------------------------- kernels -----------------------------------

__global__ void k_zero_stats(float* stats) {
    for (int i = threadIdx.x; i < 4096; i += blockDim.x) stats[i] = 0.f;
}

// pre0 = x @ w_in  (32768x6 @ 6x64) + per-channel stats
__global__ void k_in_gemm(const float* __restrict__ x, const float* __restrict__ w,
                          float* __restrict__ pre, float* __restrict__ stats) {
    __shared__ float xs[128*6];
    __shared__ float wsm[6*64];
    __shared__ float red[4][64];
    int t = threadIdx.x;
    int r0 = blockIdx.x * 128;
    for (int e = t; e < 768; e += 256) xs[e] = x[r0*6 + e];
    for (int e = t; e < 384; e += 256) wsm[e] = w[e];
    __syncthreads();
    int m = t & 63, rg = t >> 6;
    float s = 0.f, s2 = 0.f;
    for (int r = rg; r < 128; r += 4) {
        float v = 0.f;
        #pragma unroll
        for (int k = 0; k < 6; k++) v += xs[r*6+k] * wsm[k*64+m];
        pre[(r0 + r)*64 + m] = v;
        s += v; s2 += v*v;
    }
    red[rg][m] = s; __syncthreads();
    if (rg == 0) atomicAdd(&stats[ST0 + m], red[0][m]+red[1][m]+red[2][m]+red[3][m]);
    __syncthreads();
    red[rg][m] = s2; __syncthreads();
    if (rg == 0) atomicAdd(&stats[ST0 + 64 + m], red[0][m]+red[1][m]+red[2][m]+red[3][m]);
}

__global__ void k_finalize(const float* __restrict__ stats, float* __restrict__ ss,
                           int base, int C, float invcnt,
                           const float* __restrict__ g, const float* __restrict__ b) {
    int c = blockIdx.x*blockDim.x + threadIdx.x;
    if (c >= C) return;
    float mean = stats[base + c] * invcnt;
    float var  = stats[base + C + c] * invcnt - mean*mean;
    float sc = g[c] * rsqrtf(var + EPSV);
    ss[base + c]     = sc;
    ss[base + C + c] = b[c] - mean*sc;
}

__global__ void k_apply(float* __restrict__ buf, const float* __restrict__ ss,
                        int base, int C, int total) {
    int i = blockIdx.x*blockDim.x + threadIdx.x;
    if (i >= total) return;
    int c = i & (C-1);
    float v = ss[base+c]*buf[i] + ss[base+C+c];
    buf[i] = v > 0.f ? v : 0.2f*v;
}

__global__ void k_apply_ec(const float* __restrict__ O, float* __restrict__ H,
                           const float* __restrict__ ss, int base, int C, int total) {
    int i = blockIdx.x*blockDim.x + threadIdx.x;
    if (i >= total) return;
    int c = i & (C-1);
    float v = O[i];
    float r;
    if (v == NEG_INF) r = 0.f;
    else { float z = ss[base+c]*v + ss[base+C+c]; r = z > 0.f ? z : 0.2f*z; }
    H[i] = r;
}

// ----- E1: per-batch KNN (Kahan fp32, build-invariant) + A/B GEMMs + pre1 stats -----
template<int C_IN, int C_MID>
__global__ void k_e1(const float* __restrict__ X, const float* __restrict__ w_a,
                     float* __restrict__ gA, float* __restrict__ gB,
                     int* __restrict__ gidx, float* __restrict__ stats, int sbase)
{
    extern __shared__ float sm[];
    const int XST = C_IN + 1;
    float* Xs    = sm;                      // 64*XST
    float* sq    = Xs + 64*XST;             // 64
    int*   idx_s = (int*)(sq + 64);         // 1024

    int b = blockIdx.x;
    int t = threadIdx.x;
    const float* Xb = X + (size_t)b*64*C_IN;

    for (int e = t; e < 64*C_IN; e += 256) {
        int i = e / C_IN, k = e % C_IN;
        Xs[i*XST + k] = Xb[e];
    }
    __syncthreads();
    if (t < 64) {
        float s = 0.f, c = 0.f;
        for (int k = 0; k < C_IN; k++) {
            float v = Xs[t*XST+k];
            kahan_fma(v, v, s, c);
        }
        sq[t] = __fsub_rn(s, c);
    }
    __syncthreads();

    // KNN: warp per row, iterative argmin, stable (d, index) tie-break
    {
        int w = t >> 5, l = t & 31;
        for (int i = w; i < 64; i += 8) {
            float s0 = 0.f, c0 = 0.f, s1 = 0.f, c1 = 0.f;
            for (int k = 0; k < C_IN; k++) {
                float xi = Xs[i*XST+k];
                kahan_fma(xi, Xs[l*XST+k],      s0, c0);
                kahan_fma(xi, Xs[(l+32)*XST+k], s1, c1);
            }
            float f0 = __fsub_rn(s0, c0);
            float f1 = __fsub_rn(s1, c1);
            float base0 = __fadd_rn(sq[i], sq[l]);
            float base1 = __fadd_rn(sq[i], sq[l+32]);
            float my0 = __fmaf_rn(-2.f, f0, base0);
            float my1 = __fmaf_rn(-2.f, f1, base1);
            for (int pick = 0; pick <= KK; pick++) {
                float dm; int jm;
                if (my0 <= my1) { dm = my0; jm = l; } else { dm = my1; jm = l+32; }
                #pragma unroll
                for (int off = 16; off; off >>= 1) {
                    float od = __shfl_xor_sync(0xffffffffu, dm, off);
                    int   oj = __shfl_xor_sync(0xffffffffu, jm, off);
                    if (od < dm || (od == dm && oj < jm)) { dm = od; jm = oj; }
                }
                if ((jm & 31) == l) { if (jm >= 32) my1 = __int_as_float(0x7f800000); else my0 = __int_as_float(0x7f800000); }
                if (pick > 0 && l == 0) {
                    idx_s[i*KK + pick - 1] = jm;
                    gidx[((size_t)b*64 + i)*KK + pick - 1] = jm;
                }
            }
        }
    }
    __syncthreads();

    // A = X@Wd, B = X@(Wn-Wd)  -> global only
    {
        const int G = 256 / C_MID;
        const int IPG = 64 / G;
        int m = t % C_MID;
        int g = t / C_MID;
        for (int i0 = g*IPG; i0 < (g+1)*IPG; i0 += 8) {
            float aa[8], bb[8];
            #pragma unroll
            for (int ii = 0; ii < 8; ii++) { aa[ii]=0.f; bb[ii]=0.f; }
            for (int k = 0; k < C_IN; k++) {
                float wn  = w_a[k*C_MID + m];
                float wd  = w_a[(C_IN + k)*C_MID + m];
                float wnd = wn - wd;
                #pragma unroll
                for (int ii = 0; ii < 8; ii++) {
                    float xv = Xs[(i0+ii)*XST + k];
                    aa[ii] += xv * wd;
                    bb[ii] += xv * wnd;
                }
            }
            #pragma unroll
            for (int ii = 0; ii < 8; ii++) {
                gA[((size_t)b*64 + i0+ii)*C_MID + m] = aa[ii];
                gB[((size_t)b*64 + i0+ii)*C_MID + m] = bb[ii];
            }
        }
    }
    __syncthreads();   // make gA/gB writes visible block-wide

    // stats of pre1 = A[c] + B[idx[c,k]]  (read back from global)
    {
        const float* Ab = gA + (size_t)b*64*C_MID;
        const float* Bb = gB + (size_t)b*64*C_MID;
        const int G = 256 / C_MID;
        int m = t % C_MID, rep = t / C_MID;
        float s = 0.f, s2 = 0.f;
        for (int r = rep; r < 64*KK; r += G) {
            int c = r >> 4;
            int nbr = idx_s[r];
            float v = Ab[c*C_MID + m] + Bb[nbr*C_MID + m];
            s += v; s2 += v*v;
        }
        atomicAdd(&stats[sbase + m], s);
        atomicAdd(&stats[sbase + C_MID + m], s2);
    }
}

// ----- E3: build h rows, GEMM with w_b from L1/L2, scatter-max + pre2 stats -----
template<int C_MID, int C_OUT>
__global__ void k_e3(const float* __restrict__ gA, const float* __restrict__ gB,
                     const int* __restrict__ gidx, const float* __restrict__ w_b,
                     const float* __restrict__ ss, int ssbase,
                     float* __restrict__ stats, int sbase,
                     float* __restrict__ O)
{
    extern __shared__ float sm[];
    const int HST = C_MID + 1;
    float* Hs  = sm;                        // 32*HST
    float* scs = Hs + 32*HST;               // C_MID
    float* shs = scs + C_MID;               // C_MID
    unsigned* outu = (unsigned*)(shs + C_MID);  // 4096
    int* idx_s = (int*)(outu + 4096);           // 1024

    int b  = blockIdx.x;
    int cb = blockIdx.y * 64;
    int t  = threadIdx.x;

    for (int e = t; e < 1024; e += 256) idx_s[e] = gidx[b*1024 + e];
    for (int e = t; e < C_MID; e += 256) {
        scs[e] = ss[ssbase + e];
        shs[e] = ss[ssbase + C_MID + e];
    }
    for (int e = t; e < 4096; e += 256) outu[e] = 0u;
    __syncthreads();

    const float* Ab = gA + (size_t)b*64*C_MID;
    const float* Bb = gB + (size_t)b*64*C_MID;
    const float4* Wg = (const float4*)(w_b + cb);   // row stride C_OUT/4 float4s
    const int WS = C_OUT >> 2;

    int cg = t & 15;
    int rg = t >> 4;
    int c0 = cg * 4;
    float csum[4] = {0,0,0,0}, csq[4] = {0,0,0,0};

    for (int tt = 0; tt < 32; tt++) {
        for (int e = t; e < 32*C_MID; e += 256) {
            int rr = e / C_MID, m = e % C_MID;
            int r = tt*32 + rr;
            int c = r >> 4;
            int nbr = idx_s[r];
            float v = Ab[c*C_MID + m] + Bb[nbr*C_MID + m];
            v = scs[m]*v + shs[m];
            Hs[rr*HST + m] = v > 0.f ? v : 0.2f*v;
        }
        __syncthreads();
        int rr0 = rg*2, rr1 = rr0 + 1;
        float a00=0,a01=0,a02=0,a03=0,a10=0,a11=0,a12=0,a13=0;
        #pragma unroll 4
        for (int kk = 0; kk < C_MID; kk++) {
            float h0 = Hs[rr0*HST + kk];
            float h1 = Hs[rr1*HST + kk];
            float4 wv = __ldg(&Wg[kk*WS + cg]);
            a00 += h0*wv.x; a01 += h0*wv.y; a02 += h0*wv.z; a03 += h0*wv.w;
            a10 += h1*wv.x; a11 += h1*wv.y; a12 += h1*wv.z; a13 += h1*wv.w;
        }
        {
            int r = tt*32 + rr0;
            int n = idx_s[r];
            csum[0]+=a00; csq[0]+=a00*a00; atomicMax(&outu[n*64+c0+0], enc_f(a00));
            csum[1]+=a01; csq[1]+=a01*a01; atomicMax(&outu[n*64+c0+1], enc_f(a01));
            csum[2]+=a02; csq[2]+=a02*a02; atomicMax(&outu[n*64+c0+2], enc_f(a02));
            csum[3]+=a03; csq[3]+=a03*a03; atomicMax(&outu[n*64+c0+3], enc_f(a03));
            r = tt*32 + rr1;
            n = idx_s[r];
            csum[0]+=a10; csq[0]+=a10*a10; atomicMax(&outu[n*64+c0+0], enc_f(a10));
            csum[1]+=a11; csq[1]+=a11*a11; atomicMax(&outu[n*64+c0+1], enc_f(a11));
            csum[2]+=a12; csq[2]+=a12*a12; atomicMax(&outu[n*64+c0+2], enc_f(a12));
            csum[3]+=a13; csq[3]+=a13*a13; atomicMax(&outu[n*64+c0+3], enc_f(a13));
        }
        __syncthreads();
    }
    #pragma unroll
    for (int j = 0; j < 4; j++) {
        atomicAdd(&stats[sbase + cb + c0 + j], csum[j]);
        atomicAdd(&stats[sbase + C_OUT + cb + c0 + j], csq[j]);
    }
    for (int e = t; e < 4096; e += 256) {
        unsigned u = outu[e];
        float v = u ? dec_f(u) : NEG_INF;
        int n = e >> 6, j = e & 63;
        O[((size_t)b*64 + n)*C_OUT + cb + j] = v;
    }
}

// pooled = [mean_n h, max_n h]
__global__ void k_pool(const float* __restrict__ h1, const float* __restrict__ h2,
                       const float* __restrict__ h3, float* __restrict__ pool) {
    int b = blockIdx.x, t = threadIdx.x;
    for (int ch = t; ch < 448; ch += 256) {
        const float* src; int C, cc;
        if (ch < 64)       { src = h1; C = 64;  cc = ch; }
        else if (ch < 192) { src = h2; C = 128; cc = ch - 64; }
        else               { src = h3; C = 256; cc = ch - 192; }
        float s = 0.f, mxv = NEG_INF;
        for (int n = 0; n < 64; n++) {
            float v = src[((size_t)b*64 + n)*C + cc];
            s += v; mxv = fmaxf(mxv, v);
        }
        pool[b*896 + ch]       = s * (1.f/64.f);
        pool[b*896 + 448 + ch] = mxv;
    }
}

// classifier GEMM (tiled 16x16)
__global__ void k_gemm(const float* __restrict__ A, const float* __restrict__ W,
                       const float* __restrict__ bias, float* __restrict__ Cout,
                       int M, int Kd, int Nn, float* stats, int sbase) {
    __shared__ float as[16][17], ws[16][17];
    int tx = threadIdx.x, ty = threadIdx.y;
    int row = blockIdx.y*16 + ty;
    int col = blockIdx.x*16 + tx;
    float acc = 0.f;
    for (int k0 = 0; k0 < Kd; k0 += 16) {
        as[ty][tx] = (row < M && k0+tx < Kd) ? A[row*Kd + k0 + tx] : 0.f;
        ws[ty][tx] = (k0+ty < Kd && col < Nn) ? W[(k0+ty)*Nn + col] : 0.f;
        __syncthreads();
        #pragma unroll
        for (int kk = 0; kk < 16; kk++) acc += as[ty][kk]*ws[kk][tx];
        __syncthreads();
    }
    if (row < M && col < Nn) {
        if (bias) acc += bias[col];
        Cout[row*Nn + col] = acc;
        if (stats) {
            atomicAdd(&stats[sbase + col], acc);
            atomicAdd(&stats[sbase + Nn + col], acc*acc);
        }
    }
}

// ------------------------- host launcher -----------------------------
static inline size_t e1_smem(int cin) {
    return (size_t)(64*(cin+1) + 64)*4 + 1024*4;
}
static inline size_t e3_smem(int cmid) {
    return (size_t)(32*(cmid+1) + 2*cmid)*4 + 4096*4 + 1024*4;
}

extern "C" void kernel_launch(void* const* d_in, const int* in_sizes, int n_in,
                              void* d_out, int out_size) {
    static const int ALPHA[31] = {30,7,26,17,6,20,11,0,21,12,1,22,13,2,23,14,3,
                                  24,15,4,25,16,5,27,18,8,28,19,9,29,10};
    const void* in[31];
    bool refOrder = (in_sizes[0] == ROWS*6);
    for (int i = 0; i < 31; i++) in[i] = refOrder ? d_in[i] : d_in[ALPHA[i]];

    const float* x    = (const float*)in[0];
    const float* w_in = (const float*)in[2];
    const float* g_in = (const float*)in[3];
    const float* b_in = (const float*)in[4];
    const float* w1a  = (const float*)in[5];
    const float* g1a  = (const float*)in[6];
    const float* b1a  = (const float*)in[7];
    const float* w1b  = (const float*)in[8];
    const float* g1b  = (const float*)in[9];
    const float* b1b  = (const float*)in[10];
    const float* w2a  = (const float*)in[11];
    const float* g2a  = (const float*)in[12];
    const float* b2a  = (const float*)in[13];
    const float* w2b  = (const float*)in[14];
    const float* g2b  = (const float*)in[15];
    const float* b2b  = (const float*)in[16];
    const float* w3a  = (const float*)in[17];
    const float* g3a  = (const float*)in[18];
    const float* b3a  = (const float*)in[19];
    const float* w3b  = (const float*)in[20];
    const float* g3b  = (const float*)in[21];
    const float* b3b  = (const float*)in[22];
    const float* wc1  = (const float*)in[23];
    const float* gc1  = (const float*)in[24];
    const float* bc1  = (const float*)in[25];
    const float* wc2  = (const float*)in[26];
    const float* gc2  = (const float*)in[27];
    const float* bc2  = (const float*)in[28];
    const float* wc3  = (const float*)in[29];
    const float* bc3  = (const float*)in[30];
    float* out = (float*)d_out;

    float *h0, *h1, *h2, *h3, *Abuf, *Bbuf, *Obuf, *pool, *z1, *z2, *stats, *ss;
    int* idxp;
    cudaGetSymbolAddress((void**)&h0, g_h0);
    cudaGetSymbolAddress((void**)&h1, g_h1);
    cudaGetSymbolAddress((void**)&h2, g_h2);
    cudaGetSymbolAddress((void**)&h3, g_h3);
    cudaGetSymbolAddress((void**)&Abuf, g_Abuf);
    cudaGetSymbolAddress((void**)&Bbuf, g_Bbuf);
    cudaGetSymbolAddress((void**)&Obuf, g_Obuf);
    cudaGetSymbolAddress((void**)&idxp, g_idxbuf);
    cudaGetSymbolAddress((void**)&pool, g_pool);
    cudaGetSymbolAddress((void**)&z1, g_z1);
    cudaGetSymbolAddress((void**)&z2, g_z2);
    cudaGetSymbolAddress((void**)&stats, g_stats);
    cudaGetSymbolAddress((void**)&ss, g_ss);

    cudaFuncSetAttribute(k_e1<64,64>,   cudaFuncAttributeMaxDynamicSharedMemorySize, (int)e1_smem(64));
    cudaFuncSetAttribute(k_e1<64,128>,  cudaFuncAttributeMaxDynamicSharedMemorySize, (int)e1_smem(64));
    cudaFuncSetAttribute(k_e1<128,256>, cudaFuncAttributeMaxDynamicSharedMemorySize, (int)e1_smem(128));
    cudaFuncSetAttribute(k_e3<64,64>,   cudaFuncAttributeMaxDynamicSharedMemorySize, (int)e3_smem(64));
    cudaFuncSetAttribute(k_e3<128,128>, cudaFuncAttributeMaxDynamicSharedMemorySize, (int)e3_smem(128));
    cudaFuncSetAttribute(k_e3<256,256>, cudaFuncAttributeMaxDynamicSharedMemorySize, (int)e3_smem(256));

    k_zero_stats<<<1, 256>>>(stats);

    // stage 0: input MLP
    k_in_gemm<<<256, 256>>>(x, w_in, h0, stats);
    k_finalize<<<1, 512>>>(stats, ss, ST0, 64, 1.f/ROWS, g_in, b_in);
    k_apply<<<ROWS*64/256, 256>>>(h0, ss, ST0, 64, ROWS*64);

    // conv1
    k_e1<64,64><<<BB, 256, e1_smem(64)>>>(h0, w1a, Abuf, Bbuf, idxp, stats, ST1);
    k_finalize<<<1, 512>>>(stats, ss, ST1, 64, 1.f/(ROWS*KK), g1a, b1a);
    k_e3<64,64><<<dim3(BB,1), 256, e3_smem(64)>>>(Abuf, Bbuf, idxp, w1b, ss, ST1, stats, ST2, Obuf);
    k_finalize<<<1, 512>>>(stats, ss, ST2, 64, 1.f/(ROWS*KK), g1b, b1b);
    k_apply_ec<<<ROWS*64/256, 256>>>(Obuf, h1, ss, ST2, 64, ROWS*64);

    // conv2
    k_e1<64,128><<<BB, 256, e1_smem(64)>>>(h1, w2a, Abuf, Bbuf, idxp, stats, ST3);
    k_finalize<<<1, 512>>>(stats, ss, ST3, 128, 1.f/(ROWS*KK), g2a, b2a);
    k_e3<128,128><<<dim3(BB,2), 256, e3_smem(128)>>>(Abuf, Bbuf, idxp, w2b, ss, ST3, stats, ST4, Obuf);
    k_finalize<<<1, 512>>>(stats, ss, ST4, 128, 1.f/(ROWS*KK), g2b, b2b);
    k_apply_ec<<<ROWS*128/256, 256>>>(Obuf, h2, ss, ST4, 128, ROWS*128);

    // conv3
    k_e1<128,256><<<BB, 256, e1_smem(128)>>>(h2, w3a, Abuf, Bbuf, idxp, stats, ST5);
    k_finalize<<<1, 512>>>(stats, ss, ST5, 256, 1.f/(ROWS*KK), g3a, b3a);
    k_e3<256,256><<<dim3(BB,4), 256, e3_smem(256)>>>(Abuf, Bbuf, idxp, w3b, ss, ST5, stats, ST6, Obuf);
    k_finalize<<<1, 512>>>(stats, ss, ST6, 256, 1.f/(ROWS*KK), g3b, b3b);
    k_apply_ec<<<ROWS*256/256, 256>>>(Obuf, h3, ss, ST6, 256, ROWS*256);

    // pooling + classifier
    k_pool<<<BB, 256>>>(h1, h2, h3, pool);

    k_gemm<<<dim3(512/16, BB/16), dim3(16,16)>>>(pool, wc1, nullptr, z1, BB, 896, 512, stats, ST7);
    k_finalize<<<1, 512>>>(stats, ss, ST7, 512, 1.f/BB, gc1, bc1);
    k_apply<<<BB*512/256, 256>>>(z1, ss, ST7, 512, BB*512);

    k_gemm<<<dim3(256/16, BB/16), dim3(16,16)>>>(z1, wc2, nullptr, z2, BB, 512, 256, stats, ST8);
    k_finalize<<<1, 512>>>(stats, ss, ST8, 256, 1.f/BB, gc2, bc2);
    k_apply<<<BB*256/256, 256>>>(z2, ss, ST8, 256, BB*256);

    k_gemm<<<dim3(1, BB/16), dim3(16,16)>>>(z2, wc3, bc3, out, BB, 256, 2, nullptr, 0);
}